// round 14
// baseline (speedup 1.0000x reference)
#include <cuda_runtime.h>

#define BB 4
#define NN 8192
#define G 48
#define G3 (G * G * G)
#define CAP 8
#define GL 5.0f
#define CS (2.0f * GL / (float)G)       // 0.2083333 cell size
#define CS2 (CS * CS)
#define MAXSPILL 8192
#define PREP_THREADS 64
#define PREP_BLOCKS (BB * NN / 4 / PREP_THREADS)
#define ZERO_TOTAL (2 * BB * G3)
#define NQ (2 * BB * NN)                // 65536 total queries
#define Q2BLOCKS 64                     // phase-2 blocks (worklist is small)

// Device-global scratch (no allocations allowed)
__device__ float4 g_flat[2][BB][NN];            // [0]=clean, [1]=predp
__device__ int    g_cnt [2][BB][G3];            // per-cell counts
__device__ float4 g_cell[2][BB][G3][CAP];       // per-cell points (true coords)
__device__ float4 g_spill[2][BB][MAXSPILL];     // overflow points (exact)
__device__ int    g_spillcnt[2][BB];
__device__ int    g_nv[BB];
__device__ float  g_l1sum;
__device__ float  g_cd;
__device__ int    g_work_idx[NQ];
__device__ float  g_work_best[NQ];
__device__ int    g_nwork;
__device__ int    g_ticket;

__global__ void zero_kernel() {
    int idx = blockIdx.x * blockDim.x + threadIdx.x;   // covers ZERO_TOTAL exactly
    ((int*)g_cnt)[idx] = 0;
    if (idx < 8)  ((int*)g_spillcnt)[idx] = 0;
    if (idx < BB) g_nv[idx] = 0;
    if (idx == 0) { g_l1sum = 0.0f; g_cd = 0.0f; g_nwork = 0; g_ticket = 0; }
}

__device__ __forceinline__ int cell_of(float x, float y, float z) {
    int cx = min(max((int)floorf((x + GL) * (1.0f / CS)), 0), G - 1);
    int cy = min(max((int)floorf((y + GL) * (1.0f / CS)), 0), G - 1);
    int cz = min(max((int)floorf((z + GL) * (1.0f / CS)), 0), G - 1);
    return (cz * G + cy) * G + cx;
}

__device__ __forceinline__ void grid_insert(int s, int b, float x, float y, float z) {
    int cell = cell_of(x, y, z);
    int k = atomicAdd(&g_cnt[s][b][cell], 1);
    if (k < CAP) {
        g_cell[s][b][cell][k] = make_float4(x, y, z, 0.0f);
    } else {
        int j = atomicAdd(&g_spillcnt[s][b], 1);
        if (j < MAXSPILL) g_spill[s][b][j] = make_float4(x, y, z, 0.0f);
    }
}

__global__ void __launch_bounds__(PREP_THREADS)
prep_kernel(const float* __restrict__ pred,
            const float* __restrict__ target,
            const int*   __restrict__ mask,
            const float* __restrict__ points) {
    int gid = blockIdx.x * PREP_THREADS + threadIdx.x;   // 0..8191, 4 points each
    int b = gid >> 11;

    const float4* P4 = (const float4*)(pred   + (size_t)gid * 12);
    const float4* T4 = (const float4*)(target + (size_t)gid * 12);
    const float4* X4 = (const float4*)(points + (size_t)gid * 12);
    float4 pA = P4[0], pB = P4[1], pC = P4[2];
    float4 tA = T4[0], tB = T4[1], tC = T4[2];
    float4 xA = X4[0], xB = X4[1], xC = X4[2];
    int4 mm = *(const int4*)(mask + (size_t)gid * 4);

    float px[4] = {pA.x, pA.w, pB.z, pC.y};
    float py[4] = {pA.y, pB.x, pB.w, pC.z};
    float pz[4] = {pA.z, pB.y, pC.x, pC.w};
    float tx[4] = {tA.x, tA.w, tB.z, tC.y};
    float ty[4] = {tA.y, tB.x, tB.w, tC.z};
    float tz[4] = {tA.z, tB.y, tC.x, tC.w};
    float xx[4] = {xA.x, xA.w, xB.z, xC.y};
    float xy[4] = {xA.y, xB.x, xB.w, xC.z};
    float xz[4] = {xA.z, xB.y, xC.x, xC.w};
    int   mk[4] = {mm.x, mm.y, mm.z, mm.w};

    int cnt = mk[0] + mk[1] + mk[2] + mk[3];
    int slot = (cnt > 0) ? atomicAdd(&g_nv[b], cnt) : 0;

    float li = 0.0f;
    #pragma unroll
    for (int k = 0; k < 4; k++) {
        if (mk[k]) {
            li += (fabsf(px[k] - tx[k]) + fabsf(py[k] - ty[k]) + fabsf(pz[k] - tz[k]))
                  * (1.0f / 3.0f);
            float c0 = xx[k] + tx[k], c1 = xy[k] + ty[k], c2 = xz[k] + tz[k];   // clean
            float q0 = xx[k] + px[k], q1 = xy[k] + py[k], q2 = xz[k] + pz[k];   // predp
            g_flat[0][b][slot] = make_float4(c0, c1, c2, 0.0f);
            g_flat[1][b][slot] = make_float4(q0, q1, q2, 0.0f);
            grid_insert(0, b, c0, c1, c2);   // set0 = clean grid
            grid_insert(1, b, q0, q1, q2);   // set1 = predp grid
            slot++;
        }
    }

    #pragma unroll
    for (int o = 16; o; o >>= 1) li += __shfl_down_sync(0xFFFFFFFFu, li, o);
    if ((threadIdx.x & 31) == 0) atomicAdd(&g_l1sum, li);
}

__device__ __forceinline__ void scan_cell(int s, int b, int cell,
                                          float qx, float qy, float qz, float& best) {
    int n = min(g_cnt[s][b][cell], CAP);
    const float4* p = g_cell[s][b][cell];
    for (int k = 0; k < n; k++) {
        float4 t = p[k];
        float dx = qx - t.x, dy = qy - t.y, dz = qz - t.z;
        float d2 = fmaf(dx, dx, fmaf(dy, dy, dz * dz));
        best = fminf(best, d2);
    }
}

// Phase 1: uniform 27-cell scan; certified -> accumulate, else -> worklist.
__global__ void __launch_bounds__(256)
query1_kernel() {
    __shared__ float red[8];
    int idx = blockIdx.x * 256 + threadIdx.x;   // covers NQ exactly
    int dir = idx >> 15;                        // BB*NN = 32768
    int r   = idx & 32767;
    int b   = r >> 13;                          // block-uniform (8192 % 256 == 0)
    int i   = r & (NN - 1);
    int nv  = g_nv[b];

    float acc = 0.0f;
    if (i < nv) {
        float4 q = g_flat[dir][b][i];
        int s = 1 - dir;
        float qx = q.x, qy = q.y, qz = q.z;
        int cx = min(max((int)floorf((qx + GL) * (1.0f / CS)), 0), G - 1);
        int cy = min(max((int)floorf((qy + GL) * (1.0f / CS)), 0), G - 1);
        int cz = min(max((int)floorf((qz + GL) * (1.0f / CS)), 0), G - 1);

        float best = 1e30f;

        // exact spill points (not covered by the grid bound)
        int sc = min(g_spillcnt[s][b], MAXSPILL);
        for (int k = 0; k < sc; k++) {
            float4 t = g_spill[s][b][k];
            float dx = qx - t.x, dy = qy - t.y, dz = qz - t.z;
            best = fminf(best, fmaf(dx, dx, fmaf(dy, dy, dz * dz)));
        }

        // fixed 27-cell cube (R=1)
        #pragma unroll
        for (int dz = -1; dz <= 1; dz++) {
            int z = cz + dz; if ((unsigned)z >= G) continue;
            #pragma unroll
            for (int dy = -1; dy <= 1; dy++) {
                int y = cy + dy; if ((unsigned)y >= G) continue;
                int rowbase = (z * G + y) * G;
                #pragma unroll
                for (int dx = -1; dx <= 1; dx++) {
                    int x = cx + dx; if ((unsigned)x >= G) continue;
                    scan_cell(s, b, rowbase + x, qx, qy, qz, best);
                }
            }
        }

        if (best <= CS2) {
            acc = best;                          // certified exact
        } else {
            int j = atomicAdd(&g_nwork, 1);      // defer to phase 2
            g_work_idx[j] = idx;
            g_work_best[j] = best;
        }
    }

    // block reduction (b uniform per block) -> one scaled atomic
    #pragma unroll
    for (int o = 16; o; o >>= 1) acc += __shfl_down_sync(0xFFFFFFFFu, acc, o);
    if ((threadIdx.x & 31) == 0) red[threadIdx.x >> 5] = acc;
    __syncthreads();
    if (threadIdx.x == 0 && nv > 0) {
        float bs = red[0] + red[1] + red[2] + red[3]
                 + red[4] + red[5] + red[6] + red[7];
        atomicAdd(&g_cd, bs / (float)nv);
    }
}

// Phase 2: shell expansion for uncertified queries; last block finalizes.
__global__ void __launch_bounds__(256)
query2_kernel(float* __restrict__ out) {
    int nw = min(g_nwork, NQ);
    for (int t = blockIdx.x * 256 + threadIdx.x; t < nw; t += Q2BLOCKS * 256) {
        int idx = g_work_idx[t];
        float best = g_work_best[t];
        int dir = idx >> 15;
        int r   = idx & 32767;
        int b   = r >> 13;
        int i   = r & (NN - 1);
        float4 q = g_flat[dir][b][i];
        int s = 1 - dir;
        float qx = q.x, qy = q.y, qz = q.z;
        int cx = min(max((int)floorf((qx + GL) * (1.0f / CS)), 0), G - 1);
        int cy = min(max((int)floorf((qy + GL) * (1.0f / CS)), 0), G - 1);
        int cz = min(max((int)floorf((qz + GL) * (1.0f / CS)), 0), G - 1);

        for (int R = 2; R < G; R++) {
            for (int dz = -R; dz <= R; dz++) {
                int z = cz + dz; if ((unsigned)z >= G) continue;
                bool fz = (dz == -R) | (dz == R);
                for (int dy = -R; dy <= R; dy++) {
                    int y = cy + dy; if ((unsigned)y >= G) continue;
                    bool face = fz | (dy == -R) | (dy == R);
                    int step = face ? 1 : 2 * R;
                    int rowbase = (z * G + y) * G;
                    for (int dx = -R; dx <= R; dx += step) {
                        int x = cx + dx; if ((unsigned)x >= G) continue;
                        scan_cell(s, b, rowbase + x, qx, qy, qz, best);
                    }
                }
            }
            float bound = (float)R * CS;
            if (best <= bound * bound) break;
        }
        atomicAdd(&g_cd, best / (float)g_nv[b]);
    }

    // finalize via ticket: last arriving block writes the scalar
    __syncthreads();
    if (threadIdx.x == 0) {
        __threadfence();
        int ticket = atomicAdd(&g_ticket, 1);
        if (ticket == Q2BLOCKS - 1) {
            int cnt = g_nv[0] + g_nv[1] + g_nv[2] + g_nv[3];
            float l1 = *((volatile float*)&g_l1sum) / (float)max(cnt, 1);
            float cd = *((volatile float*)&g_cd) / (float)BB;
            out[0] = 0.5f * (l1 + cd);
        }
    }
}

extern "C" void kernel_launch(void* const* d_in, const int* in_sizes, int n_in,
                              void* d_out, int out_size) {
    const float* pred   = (const float*)d_in[0];
    const float* target = (const float*)d_in[1];
    const int*   mask   = (const int*)d_in[2];
    const float* points = (const float*)d_in[3];

    zero_kernel<<<ZERO_TOTAL / 256, 256>>>();
    prep_kernel<<<PREP_BLOCKS, PREP_THREADS>>>(pred, target, mask, points);
    query1_kernel<<<NQ / 256, 256>>>();
    query2_kernel<<<Q2BLOCKS, 256>>>((float*)d_out);
}

// round 15
// speedup vs baseline: 2.0631x; 2.0631x over previous
#include <cuda_runtime.h>

#define BB 4
#define NN 8192
#define G 48
#define G3 (G * G * G)
#define CAP 8
#define GL 5.0f
#define CS (2.0f * GL / (float)G)       // 0.2083333 cell size
#define CS2 (CS * CS)
#define R3B (9.0f * CS2)                // (3*CS)^2 certification bound
#define MAXSPILL 8192
#define SMEM_SPILL 1024                 // spill entries staged in smem (16KB)
#define PREP_THREADS 64
#define PREP_BLOCKS (BB * NN / 4 / PREP_THREADS)
#define ZERO_TOTAL (2 * BB * G3)
#define NQ (2 * BB * NN)                // 65536 total queries
#define Q2BLOCKS 512                    // 512*8 = 4096 warps for phase 2

// Device-global scratch (no allocations allowed)
__device__ float4 g_flat[2][BB][NN];            // [0]=clean, [1]=predp
__device__ int    g_cnt [2][BB][G3];            // per-cell counts
__device__ float4 g_cell[2][BB][G3][CAP];       // per-cell points (true coords)
__device__ float4 g_spill[2][BB][MAXSPILL];     // overflow points (exact)
__device__ int    g_spillcnt[2][BB];
__device__ int    g_nv[BB];
__device__ float  g_l1sum;
__device__ float  g_cd;
__device__ int    g_work_idx[NQ];
__device__ float  g_work_best[NQ];
__device__ int    g_nwork;
__device__ int    g_ticket;

__global__ void zero_kernel() {
    int idx = blockIdx.x * blockDim.x + threadIdx.x;   // covers ZERO_TOTAL exactly
    ((int*)g_cnt)[idx] = 0;
    if (idx < 8)  ((int*)g_spillcnt)[idx] = 0;
    if (idx < BB) g_nv[idx] = 0;
    if (idx == 0) { g_l1sum = 0.0f; g_cd = 0.0f; g_nwork = 0; g_ticket = 0; }
}

__device__ __forceinline__ int cell_of(float x, float y, float z) {
    int cx = min(max((int)floorf((x + GL) * (1.0f / CS)), 0), G - 1);
    int cy = min(max((int)floorf((y + GL) * (1.0f / CS)), 0), G - 1);
    int cz = min(max((int)floorf((z + GL) * (1.0f / CS)), 0), G - 1);
    return (cz * G + cy) * G + cx;
}

__device__ __forceinline__ void grid_insert(int s, int b, float x, float y, float z) {
    int cell = cell_of(x, y, z);
    int k = atomicAdd(&g_cnt[s][b][cell], 1);
    if (k < CAP) {
        g_cell[s][b][cell][k] = make_float4(x, y, z, 0.0f);
    } else {
        int j = atomicAdd(&g_spillcnt[s][b], 1);
        if (j < MAXSPILL) g_spill[s][b][j] = make_float4(x, y, z, 0.0f);
    }
}

__global__ void __launch_bounds__(PREP_THREADS)
prep_kernel(const float* __restrict__ pred,
            const float* __restrict__ target,
            const int*   __restrict__ mask,
            const float* __restrict__ points) {
    int gid = blockIdx.x * PREP_THREADS + threadIdx.x;   // 0..8191, 4 points each
    int b = gid >> 11;

    const float4* P4 = (const float4*)(pred   + (size_t)gid * 12);
    const float4* T4 = (const float4*)(target + (size_t)gid * 12);
    const float4* X4 = (const float4*)(points + (size_t)gid * 12);
    float4 pA = P4[0], pB = P4[1], pC = P4[2];
    float4 tA = T4[0], tB = T4[1], tC = T4[2];
    float4 xA = X4[0], xB = X4[1], xC = X4[2];
    int4 mm = *(const int4*)(mask + (size_t)gid * 4);

    float px[4] = {pA.x, pA.w, pB.z, pC.y};
    float py[4] = {pA.y, pB.x, pB.w, pC.z};
    float pz[4] = {pA.z, pB.y, pC.x, pC.w};
    float tx[4] = {tA.x, tA.w, tB.z, tC.y};
    float ty[4] = {tA.y, tB.x, tB.w, tC.z};
    float tz[4] = {tA.z, tB.y, tC.x, tC.w};
    float xx[4] = {xA.x, xA.w, xB.z, xC.y};
    float xy[4] = {xA.y, xB.x, xB.w, xC.z};
    float xz[4] = {xA.z, xB.y, xC.x, xC.w};
    int   mk[4] = {mm.x, mm.y, mm.z, mm.w};

    int cnt = mk[0] + mk[1] + mk[2] + mk[3];
    int slot = (cnt > 0) ? atomicAdd(&g_nv[b], cnt) : 0;

    float li = 0.0f;
    #pragma unroll
    for (int k = 0; k < 4; k++) {
        if (mk[k]) {
            li += (fabsf(px[k] - tx[k]) + fabsf(py[k] - ty[k]) + fabsf(pz[k] - tz[k]))
                  * (1.0f / 3.0f);
            float c0 = xx[k] + tx[k], c1 = xy[k] + ty[k], c2 = xz[k] + tz[k];   // clean
            float q0 = xx[k] + px[k], q1 = xy[k] + py[k], q2 = xz[k] + pz[k];   // predp
            g_flat[0][b][slot] = make_float4(c0, c1, c2, 0.0f);
            g_flat[1][b][slot] = make_float4(q0, q1, q2, 0.0f);
            grid_insert(0, b, c0, c1, c2);   // set0 = clean grid
            grid_insert(1, b, q0, q1, q2);   // set1 = predp grid
            slot++;
        }
    }

    #pragma unroll
    for (int o = 16; o; o >>= 1) li += __shfl_down_sync(0xFFFFFFFFu, li, o);
    if ((threadIdx.x & 31) == 0) atomicAdd(&g_l1sum, li);
}

__device__ __forceinline__ void scan_cell(int s, int b, int cell,
                                          float qx, float qy, float qz, float& best) {
    int n = min(g_cnt[s][b][cell], CAP);
    const float4* p = g_cell[s][b][cell];
    for (int k = 0; k < n; k++) {
        float4 t = p[k];
        float dx = qx - t.x, dy = qy - t.y, dz = qz - t.z;
        float d2 = fmaf(dx, dx, fmaf(dy, dy, dz * dz));
        best = fminf(best, d2);
    }
}

// Phase 1: uniform 27-cell scan; certified -> accumulate, else -> worklist.
__global__ void __launch_bounds__(256)
query1_kernel() {
    __shared__ float red[8];
    __shared__ float4 sspill[SMEM_SPILL];
    int idx = blockIdx.x * 256 + threadIdx.x;   // covers NQ exactly
    int dir = idx >> 15;                        // block-uniform
    int r   = idx & 32767;
    int b   = r >> 13;                          // block-uniform
    int i   = r & (NN - 1);
    int nv  = g_nv[b];
    int s   = 1 - dir;

    // stage spill list in smem once per block (s,b block-uniform)
    int sc = min(g_spillcnt[s][b], MAXSPILL);
    int sc_sm = min(sc, SMEM_SPILL);
    for (int t = threadIdx.x; t < sc_sm; t += 256) sspill[t] = g_spill[s][b][t];
    __syncthreads();

    float acc = 0.0f;
    if (i < nv) {
        float4 q = g_flat[dir][b][i];
        float qx = q.x, qy = q.y, qz = q.z;
        int cx = min(max((int)floorf((qx + GL) * (1.0f / CS)), 0), G - 1);
        int cy = min(max((int)floorf((qy + GL) * (1.0f / CS)), 0), G - 1);
        int cz = min(max((int)floorf((qz + GL) * (1.0f / CS)), 0), G - 1);

        float best = 1e30f;

        // spill points (exact, not covered by the grid bound)
        for (int k = 0; k < sc_sm; k++) {
            float4 t = sspill[k];
            float dx = qx - t.x, dy = qy - t.y, dz = qz - t.z;
            best = fminf(best, fmaf(dx, dx, fmaf(dy, dy, dz * dz)));
        }
        for (int k = SMEM_SPILL; k < sc; k++) {       // overflow of the overflow
            float4 t = g_spill[s][b][k];
            float dx = qx - t.x, dy = qy - t.y, dz = qz - t.z;
            best = fminf(best, fmaf(dx, dx, fmaf(dy, dy, dz * dz)));
        }

        // fixed 27-cell cube (R=1)
        #pragma unroll
        for (int dz = -1; dz <= 1; dz++) {
            int z = cz + dz; if ((unsigned)z >= G) continue;
            #pragma unroll
            for (int dy = -1; dy <= 1; dy++) {
                int y = cy + dy; if ((unsigned)y >= G) continue;
                int rowbase = (z * G + y) * G;
                #pragma unroll
                for (int dx = -1; dx <= 1; dx++) {
                    int x = cx + dx; if ((unsigned)x >= G) continue;
                    scan_cell(s, b, rowbase + x, qx, qy, qz, best);
                }
            }
        }

        if (best <= CS2) {
            acc = best;                          // certified exact
        } else {
            int j = atomicAdd(&g_nwork, 1);      // defer to phase 2
            g_work_idx[j] = idx;
            g_work_best[j] = best;
        }
    }

    // block reduction -> one scaled atomic (b uniform per block)
    #pragma unroll
    for (int o = 16; o; o >>= 1) acc += __shfl_down_sync(0xFFFFFFFFu, acc, o);
    if ((threadIdx.x & 31) == 0) red[threadIdx.x >> 5] = acc;
    __syncthreads();
    if (threadIdx.x == 0 && nv > 0) {
        float bs = red[0] + red[1] + red[2] + red[3]
                 + red[4] + red[5] + red[6] + red[7];
        atomicAdd(&g_cd, bs / (float)nv);
    }
}

// Phase 2: one WARP per worklist item. Lane-parallel radius-3 cube scan;
// if still uncertified, exact warp brute-force over all db points.
__global__ void __launch_bounds__(256)
query2_kernel(float* __restrict__ out) {
    int nw = min(g_nwork, NQ);
    int lane = threadIdx.x & 31;
    int gwarp = (blockIdx.x * 256 + threadIdx.x) >> 5;
    const int nwarps = Q2BLOCKS * 8;

    for (int item = gwarp; item < nw; item += nwarps) {
        int idx = g_work_idx[item];
        int dir = idx >> 15;
        int r   = idx & 32767;
        int b   = r >> 13;
        int i   = r & (NN - 1);
        int s   = 1 - dir;
        int nvb = g_nv[b];
        float4 q = g_flat[dir][b][i];
        float qx = q.x, qy = q.y, qz = q.z;
        int cx = min(max((int)floorf((qx + GL) * (1.0f / CS)), 0), G - 1);
        int cy = min(max((int)floorf((qy + GL) * (1.0f / CS)), 0), G - 1);
        int cz = min(max((int)floorf((qz + GL) * (1.0f / CS)), 0), G - 1);

        // lane-parallel cube radius 3 (skip the cheby<=1 cells phase 1 did)
        float lb = 1e30f;
        for (int t = lane; t < 343; t += 32) {
            int dz = t / 49 - 3;
            int rem = t % 49;
            int dy = rem / 7 - 3;
            int dx = rem % 7 - 3;
            int ch = max(abs(dx), max(abs(dy), abs(dz)));
            if (ch <= 1) continue;
            int x = cx + dx, y = cy + dy, z = cz + dz;
            if ((unsigned)x >= G || (unsigned)y >= G || (unsigned)z >= G) continue;
            scan_cell(s, b, (z * G + y) * G + x, qx, qy, qz, lb);
        }
        #pragma unroll
        for (int o = 16; o; o >>= 1) lb = fminf(lb, __shfl_xor_sync(0xFFFFFFFFu, lb, o));
        float best = fminf(g_work_best[item], lb);

        if (best > R3B) {
            // exact warp brute-force over the whole db set (coalesced)
            const float4* P = g_flat[s][b];
            float bb = 1e30f;
            for (int k = lane; k < nvb; k += 32) {
                float4 t = P[k];
                float dx = qx - t.x, dy = qy - t.y, dz = qz - t.z;
                bb = fminf(bb, fmaf(dx, dx, fmaf(dy, dy, dz * dz)));
            }
            #pragma unroll
            for (int o = 16; o; o >>= 1) bb = fminf(bb, __shfl_xor_sync(0xFFFFFFFFu, bb, o));
            best = fminf(best, bb);
        }

        if (lane == 0) atomicAdd(&g_cd, best / (float)nvb);
    }

    // finalize via ticket: last arriving block writes the scalar
    __syncthreads();
    if (threadIdx.x == 0) {
        __threadfence();
        int ticket = atomicAdd(&g_ticket, 1);
        if (ticket == Q2BLOCKS - 1) {
            int cnt = g_nv[0] + g_nv[1] + g_nv[2] + g_nv[3];
            float l1 = *((volatile float*)&g_l1sum) / (float)max(cnt, 1);
            float cd = *((volatile float*)&g_cd) / (float)BB;
            out[0] = 0.5f * (l1 + cd);
        }
    }
}

extern "C" void kernel_launch(void* const* d_in, const int* in_sizes, int n_in,
                              void* d_out, int out_size) {
    const float* pred   = (const float*)d_in[0];
    const float* target = (const float*)d_in[1];
    const int*   mask   = (const int*)d_in[2];
    const float* points = (const float*)d_in[3];

    zero_kernel<<<ZERO_TOTAL / 256, 256>>>();
    prep_kernel<<<PREP_BLOCKS, PREP_THREADS>>>(pred, target, mask, points);
    query1_kernel<<<NQ / 256, 256>>>();
    query2_kernel<<<Q2BLOCKS, 256>>>((float*)d_out);
}